// round 3
// baseline (speedup 1.0000x reference)
#include <cuda_runtime.h>
#include <cstdint>

typedef unsigned long long ull;

#define NNODES 20000
#define NEDGES 640000
#define IND    256
#define HID    128
#define NG     64

// XD GEMM split-K config: one CTA per SM, 512 threads, double-buffered
#define NB   136          // nodes per block
#define KBLK 148          // ceil(20000/136)
#define STG  8            // nodes staged per round
#define NSTAGE ((NB + STG - 1) / STG)   // 17
#define XSPLIT 16         // xs_k splits per graph

// ---------------- device scratch (no allocations allowed) ----------------
__device__ int   g_C[NNODES * NG];          // [node][graph] counts, n-major
__device__ int   g_outdeg[NNODES];
__device__ int   g_cnt[NG];
__device__ float g_xdpart[KBLK][NG][IND];   // split-K partials (~9.7 MB)
__device__ float g_xspart[XSPLIT][NG][IND]; // 16 MB... actually 16*64*256*4 = 16 MB? no: 4 MB
__device__ float g_XF[2 * NG][IND];         // rows 0..63 = src-pool, 64..127 = dst-pool
__device__ float g_P[2][2 * NG][HID];       // layer activations

// ---------------- helpers ----------------
__device__ __forceinline__ ull fma2(ull a, ull b, ull c) {
    ull d;
    asm("fma.rn.f32x2 %0, %1, %2, %3;" : "=l"(d) : "l"(a), "l"(b), "l"(c));
    return d;
}

// ---------------- kernels ----------------
__global__ void zero_k() {
    int i = blockIdx.x * blockDim.x + threadIdx.x;
    int4 z = make_int4(0, 0, 0, 0);
    if (i < NNODES * NG / 4) ((int4*)g_C)[i] = z;
    if (i < NNODES / 4)      ((int4*)g_outdeg)[i] = z;
    if (i < NG / 4)          ((int4*)g_cnt)[i] = z;
}

__global__ void count_k(const int* __restrict__ src, const int* __restrict__ dst,
                        const int* __restrict__ batch) {
    __shared__ int hist[NG];
    int t = threadIdx.x;
    if (t < NG) hist[t] = 0;
    __syncthreads();
    int e = blockIdx.x * blockDim.x + t;
    if (e < NEDGES) {
        int s = src[e];
        int d = dst[e];
        int g = batch[s];
        atomicAdd(&g_C[d * NG + g], 1);
        atomicAdd(&g_outdeg[s], 1);
        atomicAdd(&hist[g], 1);
    }
    __syncthreads();
    if (t < NG && hist[t]) atomicAdd(&g_cnt[t], hist[t]);
}

// src-side pool: per-graph segmented weighted sum (batch is sorted), 16-way split
__global__ void xs_k(const float* __restrict__ x, const int* __restrict__ batch) {
    int g = blockIdx.x >> 4;
    int s = blockIdx.x & 15;
    __shared__ int sh[2];
    if (threadIdx.x < 2) {
        int target = g + threadIdx.x;
        int lo = 0, hi = NNODES;
        while (lo < hi) {
            int mid = (lo + hi) >> 1;
            if (batch[mid] < target) lo = mid + 1; else hi = mid;
        }
        sh[threadIdx.x] = lo;
    }
    __syncthreads();
    int st = sh[0], en = sh[1];
    int len = en - st;
    int a   = st + (len * s) / XSPLIT;
    int bnd = st + (len * (s + 1)) / XSPLIT;
    int tid = threadIdx.x;
    float acc0 = 0.f, acc1 = 0.f;
    int n = a;
    for (; n + 8 <= bnd; n += 8) {
        float w[8], v[8];
#pragma unroll
        for (int u = 0; u < 8; u++) w[u] = (float)g_outdeg[n + u];
#pragma unroll
        for (int u = 0; u < 8; u++) v[u] = x[(n + u) * IND + tid];
        acc0 += w[0] * v[0] + w[2] * v[2] + w[4] * v[4] + w[6] * v[6];
        acc1 += w[1] * v[1] + w[3] * v[3] + w[5] * v[5] + w[7] * v[7];
    }
    for (; n < bnd; n++) acc0 += (float)g_outdeg[n] * x[n * IND + tid];
    g_xspart[s][g][tid] = acc0 + acc1;
}

// dst-side pool: XD = C(64 x 20000) @ x(20000 x 256), split-K, fp32x2 packed FMA.
// 512 threads, 8 rows x 4 cols per thread, double-buffered smem, 1 barrier/stage.
// Counts staged pre-duplicated as {c,c} float2 -> inner loop is LDS.128 + FFMA2 only.
__global__ void __launch_bounds__(512, 1) xd_mm(const float* __restrict__ x) {
    __shared__ float  xs[2][STG * IND];    // 2 x 8 KB
    __shared__ float2 cs[2][STG * NG];     // 2 x 4 KB (duplicated counts)
    int b   = blockIdx.x;
    int n0  = b * NB;
    int tid = threadIdx.x;
    int rg  = tid >> 6;    // row group 0..7 -> rows rg*8 .. rg*8+7 (constant per warp)
    int cp  = tid & 63;    // col pair group -> float cols cp*4 .. cp*4+3

    // staging decomposition
    int ni = tid >> 6;     // node-in-stage 0..7
    int cg = tid & 63;     // float4-col for x / graph for C

    ull acc[8][2];
#pragma unroll
    for (int i = 0; i < 8; i++) { acc[i][0] = 0ull; acc[i][1] = 0ull; }

    const float4* x4 = (const float4*)x;

    // prefetch stage 0
    float4 xr; float crv;
    {
        int n = n0 + ni;
        bool ok = n < NNODES;
        xr  = ok ? x4[n * (IND / 4) + cg] : make_float4(0.f, 0.f, 0.f, 0.f);
        crv = ok ? (float)g_C[n * NG + cg] : 0.f;
    }
    ((float4*)xs[0])[tid] = xr;
    cs[0][tid] = make_float2(crv, crv);

    for (int s = 0; s < NSTAGE; s++) {
        __syncthreads();
        int buf = s & 1;
        // prefetch next stage
        float4 xr_n; float cr_n;
        if (s + 1 < NSTAGE) {
            int n = n0 + (s + 1) * STG + ni;
            bool ok = n < NNODES;
            xr_n = ok ? x4[n * (IND / 4) + cg] : make_float4(0.f, 0.f, 0.f, 0.f);
            cr_n = ok ? (float)g_C[n * NG + cg] : 0.f;
        }
        // compute on current buffer
#pragma unroll
        for (int kk = 0; kk < STG; kk++) {
            ulonglong2 xv = *(ulonglong2*)&xs[buf][kk * IND + cp * 4];     // 2 f32x2
            const float2* crow = &cs[buf][kk * NG + rg * 8];               // rows rg*8..+7, dup'd
            ulonglong2 c01 = *(ulonglong2*)&crow[0];   // rows 0,1
            ulonglong2 c23 = *(ulonglong2*)&crow[2];
            ulonglong2 c45 = *(ulonglong2*)&crow[4];
            ulonglong2 c67 = *(ulonglong2*)&crow[6];
            ull cd[8] = {c01.x, c01.y, c23.x, c23.y, c45.x, c45.y, c67.x, c67.y};
#pragma unroll
            for (int i = 0; i < 8; i++) {
                acc[i][0] = fma2(cd[i], xv.x, acc[i][0]);
                acc[i][1] = fma2(cd[i], xv.y, acc[i][1]);
            }
        }
        // store next stage into the other buffer
        if (s + 1 < NSTAGE) {
            ((float4*)xs[buf ^ 1])[tid] = xr_n;
            cs[buf ^ 1][tid] = make_float2(cr_n, cr_n);
        }
    }

    // write partials: row r, 16 B per thread per row
#pragma unroll
    for (int i = 0; i < 8; i++) {
        int r = rg * 8 + i;
        ulonglong2 v; v.x = acc[i][0]; v.y = acc[i][1];
        *(ulonglong2*)&g_xdpart[b][r][cp * 4] = v;
    }
}

// fold partials, normalize by counts (cnt==0 -> zero row)
__global__ void reduce_k() {
    int g = blockIdx.x;
    int c = threadIdx.x;
    int cnt = g_cnt[g];
    float inv = cnt > 0 ? 1.0f / (float)cnt : 0.0f;
    if (blockIdx.y == 0) {
        float a[8];
#pragma unroll
        for (int u = 0; u < 8; u++) a[u] = 0.f;
        int bq;
        for (bq = 0; bq + 8 <= KBLK; bq += 8) {
#pragma unroll
            for (int u = 0; u < 8; u++) a[u] += g_xdpart[bq + u][g][c];
        }
        float acc = ((a[0] + a[1]) + (a[2] + a[3])) + ((a[4] + a[5]) + (a[6] + a[7]));
        for (; bq < KBLK; bq++) acc += g_xdpart[bq][g][c];
        g_XF[NG + g][c] = acc * inv;
    } else {
        float a[4] = {0.f, 0.f, 0.f, 0.f};
#pragma unroll
        for (int s = 0; s < XSPLIT; s += 4) {
            a[0] += g_xspart[s + 0][g][c];
            a[1] += g_xspart[s + 1][g][c];
            a[2] += g_xspart[s + 2][g][c];
            a[3] += g_xspart[s + 3][g][c];
        }
        g_XF[g][c] = ((a[0] + a[1]) + (a[2] + a[3])) * inv;
    }
}

// one affine layer: P = (A @ W + b) * flag ; scatter into output
__global__ void head_k(const float* __restrict__ A, int K,
                       const float* __restrict__ W, const float* __restrict__ bias,
                       float* __restrict__ Pout, float* __restrict__ out, int layer) {
    __shared__ float As[16][17];
    __shared__ float Ws[16][17];
    int r0 = blockIdx.y * 16;
    int c0 = blockIdx.x * 16;
    int ty = threadIdx.y, tx = threadIdx.x;
    float acc = 0.f;
    for (int k0 = 0; k0 < K; k0 += 16) {
        As[ty][tx] = A[(r0 + ty) * K + k0 + tx];
        Ws[ty][tx] = W[(k0 + ty) * HID + c0 + tx];
        __syncthreads();
#pragma unroll
        for (int kk = 0; kk < 16; kk++) acc += As[ty][kk] * Ws[kk][tx];
        __syncthreads();
    }
    int r = r0 + ty, c = c0 + tx;
    int g = r & (NG - 1);
    float flag = g_cnt[g] > 0 ? 1.0f : 0.0f;
    float v = (acc + bias[c]) * flag;
    if (Pout) Pout[r * HID + c] = v;
    int col = layer * 256 + ((r < NG) ? 0 : HID) + c;
    out[g * 768 + col] = v;
}

// ---------------- launcher ----------------
extern "C" void kernel_launch(void* const* d_in, const int* in_sizes, int n_in,
                              void* d_out, int out_size) {
    const float* x     = (const float*)d_in[0];
    const int*   eidx  = (const int*)d_in[1];
    const int*   batch = (const int*)d_in[2];
    const float* W0 = (const float*)d_in[3];
    const float* b0 = (const float*)d_in[4];
    const float* W1 = (const float*)d_in[5];
    const float* b1 = (const float*)d_in[6];
    const float* W2 = (const float*)d_in[7];
    const float* b2 = (const float*)d_in[8];
    float* out = (float*)d_out;

    const int* src = eidx;
    const int* dst = eidx + NEDGES;

    zero_k<<<(NNODES * NG / 4 + 255) / 256, 256>>>();
    count_k<<<(NEDGES + 255) / 256, 256>>>(src, dst, batch);
    xs_k<<<NG * XSPLIT, IND>>>(x, batch);
    xd_mm<<<KBLK, 512>>>(x);
    reduce_k<<<dim3(NG, 2), IND>>>();

    float *P0, *P1;
    cudaGetSymbolAddress((void**)&P0, g_P);
    P1 = P0 + 2 * NG * HID;
    float* XF;
    cudaGetSymbolAddress((void**)&XF, g_XF);

    dim3 hb(16, 16), hg(HID / 16, 2 * NG / 16);
    head_k<<<hg, hb>>>(XF, IND, W0, b0, P0, out, 0);
    head_k<<<hg, hb>>>(P0, HID, W1, b1, P1, out, 1);
    head_k<<<hg, hb>>>(P1, HID, W2, b2, nullptr, out, 2);
}